// round 5
// baseline (speedup 1.0000x reference)
#include <cuda_runtime.h>
#include <cstdint>
#include <math.h>

// LSTM_2370821948014 — round 4: mma.sync tf32, vectorized fragment loads +
// triple-buffered cp.async.bulk weight pipeline.
//
// B=65536, I=128, H=256, O=256, K=384.
// Kernel 1 (repack): weights -> 60 x 32KB tiles; rows gate-interleaved; k
//   values stored as (k, k+4) u64 pairs with XOR bank swizzle; cvt.rna.tf32.
// Kernel 2 (main): 1024 CTAs x 64 rows. A staged once in SMEM in a
//   "lane-sectioned" layout (A'[r][lq*100+j] = A[r][4j+lq]) so each thread's
//   per-tile A fragment is 2 x LDS.128. W tiles triple-buffered via
//   cp.async.bulk + mbarrier (prefetch distance 2). 8 warps (2M x 4N), warp
//   tile 32x64, mma.sync.m16n8k8.tf32. Gate epilogue in-register; logits
//   log_softmax via shfl + SMEM cross-warp reduce.

static constexpr int BATCH = 65536;
static constexpr int ODIM  = 256;
static constexpr int KDIM  = 384;
static constexpr int MT    = 64;          // rows per CTA
static constexpr int THREADS = 256;
static constexpr int NTILES  = 60;        // 5 chunks x 12 k-tiles
static constexpr int TILE_U32 = 8192;     // 256 rows x 32 k (32KB)
static constexpr int NBUF = 3;

// SMEM layout (bytes)
static constexpr int PA      = 400;                   // A pitch in u32
static constexpr int SM_A    = 0;                     // 64*400*4 = 102400
static constexpr int SM_W    = 102400;                // 3 x 32768
static constexpr int WB      = 32768;
static constexpr int SM_BIAS = SM_W + NBUF * WB;      // 200704, 1280 floats
static constexpr int SM_REDM = SM_BIAS + 5120;        // 205824
static constexpr int SM_REDS = SM_REDM + 1024;        // 206848
static constexpr int SM_MB   = SM_REDS + 1024;        // 207872
static constexpr int SMEM_TOTAL = SM_MB + 32;         // 207904

__device__ uint32_t w_packed[NTILES * TILE_U32];      // ~1.97MB scratch

// ---------------- helpers ----------------

__device__ __forceinline__ uint32_t smem_u32(const void* p) {
    uint32_t a;
    asm("{ .reg .u64 t; cvta.to.shared.u64 t, %1; cvt.u32.u64 %0, t; }"
        : "=r"(a) : "l"(p));
    return a;
}

__device__ __forceinline__ uint32_t f2tf(float x) {
    uint32_t u;
    asm("cvt.rna.tf32.f32 %0, %1;" : "=r"(u) : "f"(x));
    return u;
}

__device__ __forceinline__ void mbar_init(uint32_t a) {
    asm volatile("mbarrier.init.shared.b64 [%0], %1;" :: "r"(a), "r"(1u) : "memory");
}

__device__ __forceinline__ void mbar_expect_tx(uint32_t a, uint32_t bytes) {
    asm volatile("mbarrier.arrive.expect_tx.shared.b64 _, [%0], %1;"
                 :: "r"(a), "r"(bytes) : "memory");
}

__device__ __forceinline__ void mbar_wait(uint32_t a, uint32_t parity) {
    asm volatile(
        "{\n\t"
        ".reg .pred P;\n\t"
        "W%=:\n\t"
        "mbarrier.try_wait.parity.acquire.cta.shared::cta.b64 P, [%0], %1, 0x989680;\n\t"
        "@P bra D%=;\n\t"
        "bra W%=;\n\t"
        "D%=:\n\t"
        "}"
        :: "r"(a), "r"(parity) : "memory");
}

__device__ __forceinline__ void bulk_ld(uint32_t dst, const void* src,
                                        uint32_t bytes, uint32_t mbar) {
    asm volatile(
        "cp.async.bulk.shared::cluster.global.mbarrier::complete_tx::bytes "
        "[%0], [%1], %2, [%3];"
        :: "r"(dst), "l"(src), "r"(bytes), "r"(mbar) : "memory");
}

__device__ __forceinline__ void mma8(float* d, const uint32_t* a,
                                     uint32_t b0, uint32_t b1) {
    asm volatile(
        "mma.sync.aligned.m16n8k8.row.col.f32.tf32.tf32.f32 "
        "{%0,%1,%2,%3}, {%4,%5,%6,%7}, {%8,%9}, {%0,%1,%2,%3};"
        : "+f"(d[0]), "+f"(d[1]), "+f"(d[2]), "+f"(d[3])
        : "r"(a[0]), "r"(a[1]), "r"(a[2]), "r"(a[3]), "r"(b0), "r"(b1));
}

__device__ __forceinline__ float sigf(float x) {
    return 1.0f / (1.0f + __expf(-x));
}
__device__ __forceinline__ float tanh_fast(float x) {
    x = fminf(fmaxf(x, -15.0f), 15.0f);
    float e = __expf(2.0f * x);
    return (e - 1.0f) / (e + 1.0f);
}

// ---------------- repack kernel ----------------
// tile t = chunk*12 + kk (kk = k window /32).
// Gates chunks (0..3): tile row v = wn*64 + jl8*32 + g*8 + jlo maps to
//   w_i2h row g*256 + chunk*64 + wn*16 + jl8*8 + jlo.
// Logits chunk (4): row v -> w_i2o row v.
// Within a row, k values stored as u64 pairs: pair p = (k>>3)*4 + (k&3)
// holds (k, k+4); stored at u32 index v*32 + 2*(p ^ ((v&3)<<2)) + ((k>>2)&1).

__global__ void repack_kernel(const float* __restrict__ w_i2h,
                              const float* __restrict__ w_i2o)
{
    int i = blockIdx.x * 256 + threadIdx.x;
    if (i >= NTILES * TILE_U32) return;
    int t  = i >> 13;
    int e  = i & 8191;
    int v  = e >> 5;
    int kw = e & 31;
    int chunk = t / 12;
    int kk    = t - chunk * 12;
    const float* src;
    int row;
    if (chunk < 4) {
        int wn  = v >> 6;
        int lc  = v & 63;
        int jl8 = lc >> 5;
        int g   = (lc >> 3) & 3;
        int jlo = lc & 7;
        row = g * 256 + chunk * 64 + wn * 16 + jl8 * 8 + jlo;
        src = w_i2h;
    } else {
        row = v;
        src = w_i2o;
    }
    float x = src[(size_t)row * KDIM + kk * 32 + kw];
    int p  = (kw >> 3) * 4 + (kw & 3);
    int hi = (kw >> 2) & 1;
    w_packed[t * TILE_U32 + v * 32 + 2 * (p ^ ((v & 3) << 2)) + hi] = f2tf(x);
}

// ---------------- main kernel ----------------

__global__ __launch_bounds__(THREADS, 1)
void lstm_mma_kernel(const float* __restrict__ input,
                     const float* __restrict__ hidden,
                     const float* __restrict__ b_i2h,
                     const float* __restrict__ b_i2o,
                     float* __restrict__ out)
{
    extern __shared__ char smem[];
    const uint32_t sbase = smem_u32(smem);
    const int tid  = threadIdx.x;
    const int wid  = tid >> 5;
    const int lane = tid & 31;
    const int wm   = wid >> 2;          // 0..1 (M)
    const int wn   = wid & 3;           // 0..3 (N)
    const int gID  = lane >> 2;         // 0..7
    const int lq   = lane & 3;          // 0..3
    const int rbase = blockIdx.x * MT;

    uint32_t* Au = (uint32_t*)(smem + SM_A);
    float*    bias = (float*)(smem + SM_BIAS);

    if (tid == 0)
        for (int b = 0; b < NBUF; ++b) mbar_init(sbase + SM_MB + 8 * b);
    __syncthreads();

    // prologue: issue tiles 0 and 1
    if (tid == 0) {
        mbar_expect_tx(sbase + SM_MB, WB);
        bulk_ld(sbase + SM_W, w_packed, WB, sbase + SM_MB);
        mbar_expect_tx(sbase + SM_MB + 8, WB);
        bulk_ld(sbase + SM_W + WB, w_packed + TILE_U32, WB, sbase + SM_MB + 8);
    }

    // stage A: A'[r][(k&3)*100 + (k>>2)] = tf32(A[r][k]), pitch 400 u32
    for (int idx = tid; idx < MT * 96; idx += THREADS) {
        int r  = idx / 96;
        int c4 = idx - r * 96;
        float4 v = (c4 < 32)
            ? *(const float4*)(input  + (size_t)(rbase + r) * 128 + c4 * 4)
            : *(const float4*)(hidden + (size_t)(rbase + r) * 256 + (c4 - 32) * 4);
        uint32_t* dst = Au + r * PA + c4;
        dst[0]   = f2tf(v.x);
        dst[100] = f2tf(v.y);
        dst[200] = f2tf(v.z);
        dst[300] = f2tf(v.w);
    }
    for (int i = tid; i < 1280; i += THREADS)
        bias[i] = (i < 1024) ? b_i2h[i] : b_i2o[i - 1024];
    __syncthreads();

    float* outLS = out;
    float* outNH = out + (size_t)BATCH * ODIM;

    float acc[2][8][4];
    #pragma unroll
    for (int m = 0; m < 2; ++m)
        #pragma unroll
        for (int n = 0; n < 8; ++n)
            #pragma unroll
            for (int c = 0; c < 4; ++c) acc[m][n][c] = 0.0f;

    for (int t = 0; t < NTILES; ++t) {
        const int buf = t % NBUF;
        // prefetch tile t+2 into buffer (t+2)%NBUF (its last consumer was
        // tile t-1, finished at the previous __syncthreads)
        if (t + 2 < NTILES && tid == 0) {
            int nb = (t + 2) % NBUF;
            uint32_t mb = sbase + SM_MB + 8 * nb;
            mbar_expect_tx(mb, WB);
            bulk_ld(sbase + SM_W + nb * WB,
                    w_packed + (size_t)(t + 2) * TILE_U32, WB, mb);
        }
        mbar_wait(sbase + SM_MB + 8 * buf, (t / NBUF) & 1);

        // ---- A fragments for this tile: 8 x LDS.128 ----
        const int kt8 = (t % 12) * 8;
        uint32_t areg[4][8];   // [mt*2 + half][j]  (half0: row gID, half1: +8)
        #pragma unroll
        for (int rr = 0; rr < 4; ++rr) {
            int r = wm * 32 + (rr >> 1) * 16 + (rr & 1) * 8 + gID;
            const uint32_t* p = Au + r * PA + lq * 100 + kt8;
            uint4 q0 = *(const uint4*)p;
            uint4 q1 = *(const uint4*)(p + 4);
            areg[rr][0] = q0.x; areg[rr][1] = q0.y;
            areg[rr][2] = q0.z; areg[rr][3] = q0.w;
            areg[rr][4] = q1.x; areg[rr][5] = q1.y;
            areg[rr][6] = q1.z; areg[rr][7] = q1.w;
        }

        // ---- compute: 4 k-steps x 8 nt, B via LDS.64 ----
        const uint2* Wp = (const uint2*)(smem + SM_W + buf * WB);
        #pragma unroll
        for (int ks = 0; ks < 4; ++ks) {
            uint32_t a0[4] = { areg[0][ks*2], areg[1][ks*2],
                               areg[0][ks*2+1], areg[1][ks*2+1] };
            uint32_t a1[4] = { areg[2][ks*2], areg[3][ks*2],
                               areg[2][ks*2+1], areg[3][ks*2+1] };
            const int psw = (ks * 4 + lq) ^ ((gID & 3) << 2);
            #pragma unroll
            for (int nt = 0; nt < 8; ++nt) {
                uint2 b = Wp[(wn * 64 + nt * 8 + gID) * 16 + psw];
                mma8(acc[0][nt], a0, b.x, b.y);
                mma8(acc[1][nt], a1, b.x, b.y);
            }
        }

        if ((t % 12) == 11) {
            const int chunk = t / 12;
            if (chunk < 4) {
                // ---- LSTM epilogue: all 4 gates in-register ----
                #pragma unroll
                for (int mt = 0; mt < 2; ++mt)
                    #pragma unroll
                    for (int rh = 0; rh < 2; ++rh)
                        #pragma unroll
                        for (int jl8 = 0; jl8 < 2; ++jl8) {
                            int r  = wm * 32 + mt * 16 + rh * 8 + gID;
                            int j0 = chunk * 64 + wn * 16 + jl8 * 8 + lq * 2;
                            int ci = rh * 2;
                            float h0 = acc[mt][jl8*4+0][ci]   + bias[j0];
                            float h1 = acc[mt][jl8*4+0][ci+1] + bias[j0+1];
                            float i0 = acc[mt][jl8*4+1][ci]   + bias[256+j0];
                            float i1 = acc[mt][jl8*4+1][ci+1] + bias[256+j0+1];
                            float f0 = acc[mt][jl8*4+2][ci]   + bias[512+j0];
                            float f1 = acc[mt][jl8*4+2][ci+1] + bias[512+j0+1];
                            float o0 = acc[mt][jl8*4+3][ci]   + bias[768+j0];
                            float o1 = acc[mt][jl8*4+3][ci+1] + bias[768+j0+1];
                            int k0 = 128 + j0, k1 = 129 + j0;
                            float hv0 = __uint_as_float(
                                Au[r * PA + (k0 & 3) * 100 + (k0 >> 2)]);
                            float hv1 = __uint_as_float(
                                Au[r * PA + (k1 & 3) * 100 + (k1 >> 2)]);
                            float2 nh;
                            nh.x = sigf(o0) * tanh_fast(sigf(f0) * hv0 + sigf(i0) * tanh_fast(h0));
                            nh.y = sigf(o1) * tanh_fast(sigf(f1) * hv1 + sigf(i1) * tanh_fast(h1));
                            *(float2*)(outNH + (size_t)(rbase + r) * 256 + j0) = nh;
                        }
                #pragma unroll
                for (int m = 0; m < 2; ++m)
                    #pragma unroll
                    for (int n = 0; n < 8; ++n)
                        #pragma unroll
                        for (int c = 0; c < 4; ++c) acc[m][n][c] = 0.0f;
            } else {
                // ---- logits epilogue: log_softmax ----
                float* redm = (float*)(smem + SM_REDM);
                float* reds = (float*)(smem + SM_REDS);

                #pragma unroll
                for (int mt = 0; mt < 2; ++mt)
                    #pragma unroll
                    for (int nt = 0; nt < 8; ++nt) {
                        int n0 = wn * 64 + nt * 8 + lq * 2;
                        acc[mt][nt][0] += bias[1024 + n0];
                        acc[mt][nt][1] += bias[1024 + n0 + 1];
                        acc[mt][nt][2] += bias[1024 + n0];
                        acc[mt][nt][3] += bias[1024 + n0 + 1];
                    }

                #pragma unroll
                for (int mt = 0; mt < 2; ++mt)
                    #pragma unroll
                    for (int rh = 0; rh < 2; ++rh) {
                        float m = -3.4e38f;
                        #pragma unroll
                        for (int nt = 0; nt < 8; ++nt) {
                            m = fmaxf(m, acc[mt][nt][rh*2]);
                            m = fmaxf(m, acc[mt][nt][rh*2+1]);
                        }
                        m = fmaxf(m, __shfl_xor_sync(0xffffffffu, m, 1));
                        m = fmaxf(m, __shfl_xor_sync(0xffffffffu, m, 2));
                        if (lq == 0) {
                            int r = wm * 32 + mt * 16 + rh * 8 + gID;
                            redm[r * 4 + wn] = m;
                        }
                    }
                __syncthreads();

                float M[2][2], L[2][2];
                #pragma unroll
                for (int mt = 0; mt < 2; ++mt)
                    #pragma unroll
                    for (int rh = 0; rh < 2; ++rh) {
                        int r = wm * 32 + mt * 16 + rh * 8 + gID;
                        float m = fmaxf(fmaxf(redm[r*4], redm[r*4+1]),
                                        fmaxf(redm[r*4+2], redm[r*4+3]));
                        M[mt][rh] = m;
                        float s = 0.0f;
                        #pragma unroll
                        for (int nt = 0; nt < 8; ++nt) {
                            s += __expf(acc[mt][nt][rh*2]   - m);
                            s += __expf(acc[mt][nt][rh*2+1] - m);
                        }
                        s += __shfl_xor_sync(0xffffffffu, s, 1);
                        s += __shfl_xor_sync(0xffffffffu, s, 2);
                        if (lq == 0) reds[r * 4 + wn] = s;
                    }
                __syncthreads();

                #pragma unroll
                for (int mt = 0; mt < 2; ++mt)
                    #pragma unroll
                    for (int rh = 0; rh < 2; ++rh) {
                        int r = wm * 32 + mt * 16 + rh * 8 + gID;
                        float st = reds[r*4] + reds[r*4+1] + reds[r*4+2] + reds[r*4+3];
                        L[mt][rh] = M[mt][rh] + logf(st);
                    }

                #pragma unroll
                for (int mt = 0; mt < 2; ++mt)
                    #pragma unroll
                    for (int rh = 0; rh < 2; ++rh) {
                        int r = wm * 32 + mt * 16 + rh * 8 + gID;
                        float lse = L[mt][rh];
                        #pragma unroll
                        for (int nt = 0; nt < 8; ++nt) {
                            int n0 = wn * 64 + nt * 8 + lq * 2;
                            float2 o;
                            o.x = acc[mt][nt][rh*2]   - lse;
                            o.y = acc[mt][nt][rh*2+1] - lse;
                            *(float2*)(outLS + (size_t)(rbase + r) * 256 + n0) = o;
                        }
                    }
            }
        }
        __syncthreads();   // all warps done with this W buffer before reuse
    }
}

extern "C" void kernel_launch(void* const* d_in, const int* in_sizes, int n_in,
                              void* d_out, int out_size)
{
    (void)in_sizes; (void)n_in; (void)out_size;
    const float* input  = (const float*)d_in[0];
    const float* hidden = (const float*)d_in[1];
    const float* w_i2h  = (const float*)d_in[2];
    const float* b_i2h  = (const float*)d_in[3];
    const float* w_i2o  = (const float*)d_in[4];
    const float* b_i2o  = (const float*)d_in[5];
    float* out = (float*)d_out;

    repack_kernel<<<(NTILES * TILE_U32 + 255) / 256, 256>>>(w_i2h, w_i2o);

    cudaFuncSetAttribute(lstm_mma_kernel,
                         cudaFuncAttributeMaxDynamicSharedMemorySize,
                         SMEM_TOTAL);
    lstm_mma_kernel<<<BATCH / MT, THREADS, SMEM_TOTAL>>>(
        input, hidden, b_i2h, b_i2o, out);
}

// round 6
// speedup vs baseline: 1.1460x; 1.1460x over previous
#include <cuda_runtime.h>
#include <cstdint>
#include <math.h>

// LSTM_2370821948014 — round 5: R3 structure (proven 533us) at 512 threads.
// 16 warps (2M x 8N), warp tile 32x32, occupancy 12.5% -> 25%.
//
// B=65536, I=128, H=256, O=256, K=384.
// Kernel 1 (repack): weights -> 60 x 32KB tiles, gate-interleaved rows
//   (v = wn*32 + g*8 + jlo), XOR bank swizzle, cvt.rna.tf32.
// Kernel 2 (main): 1024 CTAs x 64 rows; A staged once (tf32) pitch-388;
//   W double-buffered cp.async.bulk + mbarrier; mma.sync.m16n8k8.tf32.

static constexpr int BATCH = 65536;
static constexpr int ODIM  = 256;
static constexpr int KDIM  = 384;
static constexpr int MT    = 64;          // rows per CTA
static constexpr int THREADS = 512;
static constexpr int NTILES  = 60;        // 5 chunks x 12 k-tiles
static constexpr int TILE_U32 = 8192;     // 256 rows x 32 k (32KB)

// SMEM layout
static constexpr int PA      = 388;                   // A pitch (u32)
static constexpr int SM_A    = 0;                     // 64*388*4 = 99328
static constexpr int SM_W    = 99328;                 // 2 x 32768
static constexpr int WB      = 32768;
static constexpr int SM_BIAS = SM_W + 2 * WB;         // 164864 (1280 floats)
static constexpr int SM_REDM = SM_BIAS + 5120;        // 169984 (512 floats)
static constexpr int SM_REDS = SM_REDM + 2048;        // 172032
static constexpr int SM_MB   = SM_REDS + 2048;        // 174080
static constexpr int SMEM_TOTAL = SM_MB + 32;         // 174112

__device__ uint32_t w_packed[NTILES * TILE_U32];      // ~1.97MB scratch

// ---------------- helpers ----------------

__device__ __forceinline__ uint32_t smem_u32(const void* p) {
    uint32_t a;
    asm("{ .reg .u64 t; cvta.to.shared.u64 t, %1; cvt.u32.u64 %0, t; }"
        : "=r"(a) : "l"(p));
    return a;
}

__device__ __forceinline__ uint32_t f2tf(float x) {
    uint32_t u;
    asm("cvt.rna.tf32.f32 %0, %1;" : "=r"(u) : "f"(x));
    return u;
}

__device__ __forceinline__ void mbar_init(uint32_t a) {
    asm volatile("mbarrier.init.shared.b64 [%0], %1;" :: "r"(a), "r"(1u) : "memory");
}

__device__ __forceinline__ void mbar_expect_tx(uint32_t a, uint32_t bytes) {
    asm volatile("mbarrier.arrive.expect_tx.shared.b64 _, [%0], %1;"
                 :: "r"(a), "r"(bytes) : "memory");
}

__device__ __forceinline__ void mbar_wait(uint32_t a, uint32_t parity) {
    asm volatile(
        "{\n\t"
        ".reg .pred P;\n\t"
        "W%=:\n\t"
        "mbarrier.try_wait.parity.acquire.cta.shared::cta.b64 P, [%0], %1, 0x989680;\n\t"
        "@P bra D%=;\n\t"
        "bra W%=;\n\t"
        "D%=:\n\t"
        "}"
        :: "r"(a), "r"(parity) : "memory");
}

__device__ __forceinline__ void bulk_ld(uint32_t dst, const void* src,
                                        uint32_t bytes, uint32_t mbar) {
    asm volatile(
        "cp.async.bulk.shared::cluster.global.mbarrier::complete_tx::bytes "
        "[%0], [%1], %2, [%3];"
        :: "r"(dst), "l"(src), "r"(bytes), "r"(mbar) : "memory");
}

__device__ __forceinline__ void mma8(float* d, const uint32_t* a,
                                     uint32_t b0, uint32_t b1) {
    asm volatile(
        "mma.sync.aligned.m16n8k8.row.col.f32.tf32.tf32.f32 "
        "{%0,%1,%2,%3}, {%4,%5,%6,%7}, {%8,%9}, {%0,%1,%2,%3};"
        : "+f"(d[0]), "+f"(d[1]), "+f"(d[2]), "+f"(d[3])
        : "r"(a[0]), "r"(a[1]), "r"(a[2]), "r"(a[3]), "r"(b0), "r"(b1));
}

__device__ __forceinline__ float sigf(float x) {
    return 1.0f / (1.0f + __expf(-x));
}
__device__ __forceinline__ float tanh_fast(float x) {
    x = fminf(fmaxf(x, -15.0f), 15.0f);
    float e = __expf(2.0f * x);
    return (e - 1.0f) / (e + 1.0f);
}

// ---------------- repack kernel ----------------
// tile t = chunk*12 + kk.
// Gates chunks (0..3): tile row v = wn*32 + g*8 + jlo  maps to
//   w_i2h row g*256 + chunk*64 + wn*8 + jlo  (wn 0..7, g 0..3, jlo 0..7).
// Logits chunk (4): row v -> w_i2o row v.
// Element (v, kw) stored at u32 index v*32 + (kw ^ ((v&7)*4)).

__global__ void repack_kernel(const float* __restrict__ w_i2h,
                              const float* __restrict__ w_i2o)
{
    int i = blockIdx.x * 256 + threadIdx.x;
    if (i >= NTILES * TILE_U32) return;
    int t  = i >> 13;
    int e  = i & 8191;
    int v  = e >> 5;
    int kw = e & 31;
    int chunk = t / 12;
    int kk    = t - chunk * 12;
    const float* src;
    int row;
    if (chunk < 4) {
        int wn  = v >> 5;
        int g   = (v >> 3) & 3;
        int jlo = v & 7;
        row = g * 256 + chunk * 64 + wn * 8 + jlo;
        src = w_i2h;
    } else {
        row = v;
        src = w_i2o;
    }
    float x = src[(size_t)row * KDIM + kk * 32 + kw];
    w_packed[t * TILE_U32 + v * 32 + (kw ^ ((v & 7) * 4))] = f2tf(x);
}

// ---------------- main kernel ----------------

__global__ __launch_bounds__(THREADS, 1)
void lstm_mma_kernel(const float* __restrict__ input,
                     const float* __restrict__ hidden,
                     const float* __restrict__ b_i2h,
                     const float* __restrict__ b_i2o,
                     float* __restrict__ out)
{
    extern __shared__ char smem[];
    const uint32_t sbase = smem_u32(smem);
    const int tid  = threadIdx.x;
    const int wid  = tid >> 5;
    const int lane = tid & 31;
    const int wm   = wid >> 3;          // 0..1 (M)
    const int wn   = wid & 7;           // 0..7 (N)
    const int gID  = lane >> 2;         // 0..7
    const int lq   = lane & 3;          // 0..3
    const int sw   = gID << 2;          // B bank-swizzle term
    const int rbase = blockIdx.x * MT;

    uint32_t* Au = (uint32_t*)(smem + SM_A);
    float*    Af = (float*)(smem + SM_A);
    float*    bias = (float*)(smem + SM_BIAS);
    const uint32_t mb0 = sbase + SM_MB;
    const uint32_t mb1 = sbase + SM_MB + 8;

    if (tid == 0) { mbar_init(mb0); mbar_init(mb1); }
    __syncthreads();

    // issue tile 0 (overlaps A/bias staging)
    if (tid == 0) {
        mbar_expect_tx(mb0, WB);
        bulk_ld(sbase + SM_W, w_packed, WB, mb0);
    }

    // stage A = [input | hidden], tf32, pitch 388
    for (int idx = tid; idx < MT * 96; idx += THREADS) {
        int r  = idx / 96;
        int c4 = idx - r * 96;
        float4 v = (c4 < 32)
            ? *(const float4*)(input  + (size_t)(rbase + r) * 128 + c4 * 4)
            : *(const float4*)(hidden + (size_t)(rbase + r) * 256 + (c4 - 32) * 4);
        uint4 u;
        u.x = f2tf(v.x); u.y = f2tf(v.y); u.z = f2tf(v.z); u.w = f2tf(v.w);
        *(uint4*)(Au + r * PA + c4 * 4) = u;
    }
    for (int i = tid; i < 1280; i += THREADS)
        bias[i] = (i < 1024) ? b_i2h[i] : b_i2o[i - 1024];
    __syncthreads();

    float* outLS = out;
    float* outNH = out + (size_t)BATCH * ODIM;

    float acc[2][4][4];
    #pragma unroll
    for (int m = 0; m < 2; ++m)
        #pragma unroll
        for (int n = 0; n < 4; ++n)
            #pragma unroll
            for (int c = 0; c < 4; ++c) acc[m][n][c] = 0.0f;

    const int ra0 = (wm * 32 + gID) * PA;       // mt=0 rows gID, gID+8
    const int ra1 = (wm * 32 + 16 + gID) * PA;  // mt=1

    for (int t = 0; t < NTILES; ++t) {
        const int buf = t & 1;
        // prefetch t+1 into other buffer (its consumer t-1 done at last bar)
        if (t + 1 < NTILES && tid == 0) {
            uint32_t mb = buf ? mb0 : mb1;
            mbar_expect_tx(mb, WB);
            bulk_ld(sbase + SM_W + (buf ^ 1) * WB,
                    w_packed + (size_t)(t + 1) * TILE_U32, WB, mb);
        }
        mbar_wait(buf ? mb1 : mb0, (t >> 1) & 1);

        // ---- compute: 4 k-steps of 8 on this 32-k tile ----
        const uint32_t* Wu = (const uint32_t*)(smem + SM_W + buf * WB);
        const int kt = (t % 12) * 32;
        #pragma unroll
        for (int ks = 0; ks < 4; ++ks) {
            const int k0 = kt + ks * 8;
            uint32_t a0[4], a1[4];
            a0[0] = Au[ra0 + k0 + lq];
            a0[1] = Au[ra0 + 8 * PA + k0 + lq];
            a0[2] = Au[ra0 + k0 + lq + 4];
            a0[3] = Au[ra0 + 8 * PA + k0 + lq + 4];
            a1[0] = Au[ra1 + k0 + lq];
            a1[1] = Au[ra1 + 8 * PA + k0 + lq];
            a1[2] = Au[ra1 + k0 + lq + 4];
            a1[3] = Au[ra1 + 8 * PA + k0 + lq + 4];
            const int kk0 = ks * 8;
            #pragma unroll
            for (int nt = 0; nt < 4; ++nt) {
                const int vr = (wn * 32 + nt * 8 + gID) * 32;
                uint32_t b0 = Wu[vr + ((kk0 + lq) ^ sw)];
                uint32_t b1 = Wu[vr + ((kk0 + lq + 4) ^ sw)];
                mma8(acc[0][nt], a0, b0, b1);
                mma8(acc[1][nt], a1, b0, b1);
            }
        }

        if ((t % 12) == 11) {
            const int chunk = t / 12;
            if (chunk < 4) {
                // ---- LSTM epilogue: gates g = nt, all in-register ----
                #pragma unroll
                for (int mt = 0; mt < 2; ++mt)
                    #pragma unroll
                    for (int rh = 0; rh < 2; ++rh) {
                        int r  = wm * 32 + mt * 16 + rh * 8 + gID;
                        int j0 = chunk * 64 + wn * 8 + lq * 2;
                        int ci = rh * 2;
                        float h0 = acc[mt][0][ci]   + bias[j0];
                        float h1 = acc[mt][0][ci+1] + bias[j0+1];
                        float i0 = acc[mt][1][ci]   + bias[256+j0];
                        float i1 = acc[mt][1][ci+1] + bias[256+j0+1];
                        float f0 = acc[mt][2][ci]   + bias[512+j0];
                        float f1 = acc[mt][2][ci+1] + bias[512+j0+1];
                        float o0 = acc[mt][3][ci]   + bias[768+j0];
                        float o1 = acc[mt][3][ci+1] + bias[768+j0+1];
                        float hv0 = Af[r * PA + 128 + j0];
                        float hv1 = Af[r * PA + 128 + j0 + 1];
                        float2 nh;
                        nh.x = sigf(o0) * tanh_fast(sigf(f0) * hv0 + sigf(i0) * tanh_fast(h0));
                        nh.y = sigf(o1) * tanh_fast(sigf(f1) * hv1 + sigf(i1) * tanh_fast(h1));
                        *(float2*)(outNH + (size_t)(rbase + r) * 256 + j0) = nh;
                    }
                #pragma unroll
                for (int m = 0; m < 2; ++m)
                    #pragma unroll
                    for (int n = 0; n < 4; ++n)
                        #pragma unroll
                        for (int c = 0; c < 4; ++c) acc[m][n][c] = 0.0f;
            } else {
                // ---- logits epilogue: log_softmax over 256 cols ----
                float* redm = (float*)(smem + SM_REDM);
                float* reds = (float*)(smem + SM_REDS);

                #pragma unroll
                for (int mt = 0; mt < 2; ++mt)
                    #pragma unroll
                    for (int nt = 0; nt < 4; ++nt) {
                        int n0 = wn * 32 + nt * 8 + lq * 2;
                        acc[mt][nt][0] += bias[1024 + n0];
                        acc[mt][nt][1] += bias[1024 + n0 + 1];
                        acc[mt][nt][2] += bias[1024 + n0];
                        acc[mt][nt][3] += bias[1024 + n0 + 1];
                    }

                #pragma unroll
                for (int mt = 0; mt < 2; ++mt)
                    #pragma unroll
                    for (int rh = 0; rh < 2; ++rh) {
                        float m = -3.4e38f;
                        #pragma unroll
                        for (int nt = 0; nt < 4; ++nt) {
                            m = fmaxf(m, acc[mt][nt][rh*2]);
                            m = fmaxf(m, acc[mt][nt][rh*2+1]);
                        }
                        m = fmaxf(m, __shfl_xor_sync(0xffffffffu, m, 1));
                        m = fmaxf(m, __shfl_xor_sync(0xffffffffu, m, 2));
                        if (lq == 0) {
                            int r = wm * 32 + mt * 16 + rh * 8 + gID;
                            redm[r * 8 + wn] = m;
                        }
                    }
                __syncthreads();

                float M[2][2], L[2][2];
                #pragma unroll
                for (int mt = 0; mt < 2; ++mt)
                    #pragma unroll
                    for (int rh = 0; rh < 2; ++rh) {
                        int r = wm * 32 + mt * 16 + rh * 8 + gID;
                        const float* rm = redm + r * 8;
                        float m = fmaxf(fmaxf(fmaxf(rm[0], rm[1]),
                                              fmaxf(rm[2], rm[3])),
                                        fmaxf(fmaxf(rm[4], rm[5]),
                                              fmaxf(rm[6], rm[7])));
                        M[mt][rh] = m;
                        float s = 0.0f;
                        #pragma unroll
                        for (int nt = 0; nt < 4; ++nt) {
                            s += __expf(acc[mt][nt][rh*2]   - m);
                            s += __expf(acc[mt][nt][rh*2+1] - m);
                        }
                        s += __shfl_xor_sync(0xffffffffu, s, 1);
                        s += __shfl_xor_sync(0xffffffffu, s, 2);
                        if (lq == 0) reds[r * 8 + wn] = s;
                    }
                __syncthreads();

                #pragma unroll
                for (int mt = 0; mt < 2; ++mt)
                    #pragma unroll
                    for (int rh = 0; rh < 2; ++rh) {
                        int r = wm * 32 + mt * 16 + rh * 8 + gID;
                        const float* rs = reds + r * 8;
                        float st = ((rs[0] + rs[1]) + (rs[2] + rs[3])) +
                                   ((rs[4] + rs[5]) + (rs[6] + rs[7]));
                        L[mt][rh] = M[mt][rh] + logf(st);
                    }

                #pragma unroll
                for (int mt = 0; mt < 2; ++mt)
                    #pragma unroll
                    for (int rh = 0; rh < 2; ++rh) {
                        int r = wm * 32 + mt * 16 + rh * 8 + gID;
                        float lse = L[mt][rh];
                        #pragma unroll
                        for (int nt = 0; nt < 4; ++nt) {
                            int n0 = wn * 32 + nt * 8 + lq * 2;
                            float2 o;
                            o.x = acc[mt][nt][rh*2]   - lse;
                            o.y = acc[mt][nt][rh*2+1] - lse;
                            *(float2*)(outLS + (size_t)(rbase + r) * 256 + n0) = o;
                        }
                    }
            }
        }
        __syncthreads();   // all warps done with this W buffer before reuse
    }
}

extern "C" void kernel_launch(void* const* d_in, const int* in_sizes, int n_in,
                              void* d_out, int out_size)
{
    (void)in_sizes; (void)n_in; (void)out_size;
    const float* input  = (const float*)d_in[0];
    const float* hidden = (const float*)d_in[1];
    const float* w_i2h  = (const float*)d_in[2];
    const float* b_i2h  = (const float*)d_in[3];
    const float* w_i2o  = (const float*)d_in[4];
    const float* b_i2o  = (const float*)d_in[5];
    float* out = (float*)d_out;

    repack_kernel<<<(NTILES * TILE_U32 + 255) / 256, 256>>>(w_i2h, w_i2o);

    cudaFuncSetAttribute(lstm_mma_kernel,
                         cudaFuncAttributeMaxDynamicSharedMemorySize,
                         SMEM_TOTAL);
    lstm_mma_kernel<<<BATCH / MT, THREADS, SMEM_TOTAL>>>(
        input, hidden, b_i2h, b_i2o, out);
}